// round 1
// baseline (speedup 1.0000x reference)
#include <cuda_runtime.h>
#include <math.h>

#define NPROP 512
#define CC    256
#define FCDIM 1024
#define FIN   12544   // 256*7*7
#define NCLS  7
#define NEG_INF __int_as_float(0xff800000)
#define DW_MAX 4.135166556742356f

// ---------------- device scratch (static globals; no allocs) ----------------
__device__ float g_featT[13600000];   // p2T(10.24M) p3T(2.56M) p4T(0.64M) p5T(0.16M), HWC layout
__device__ float g_convwT[7077888];   // [s*4+l][ic][k][oc]
__device__ float g_xfeat[NPROP * FIN];
__device__ float g_h[NPROP * FCDIM];
__device__ float g_boxes[NPROP * 4];
__device__ float g_ssum[NPROP * NCLS];

// ---------------- init: copy proposals, zero score accumulator -------------
__global__ void k_init(const float* proposals) {
    int t = blockIdx.x * blockDim.x + threadIdx.x;
    if (t < NPROP * 4) g_boxes[t] = proposals[t];
    if (t < NPROP * NCLS) g_ssum[t] = 0.f;
}

// ---------------- NCHW(256,HW) -> HWC transpose into g_featT ---------------
__global__ void k_transpose(const float* __restrict__ in, int HW, int outOff) {
    __shared__ float tile[32][33];
    int p0 = blockIdx.x * 32, c0 = blockIdx.y * 32;
    int tx = threadIdx.x, ty = threadIdx.y;
    for (int i = ty; i < 32; i += 8) {
        int p = p0 + tx;
        if (p < HW) tile[i][tx] = in[(c0 + i) * HW + p];
    }
    __syncthreads();
    for (int i = ty; i < 32; i += 8) {
        int p = p0 + i;
        if (p < HW) g_featT[outOff + p * 256 + (c0 + tx)] = tile[tx][i];
    }
}

// ------------- conv weights [sl][oc][ic][3][3] -> [sl][ic][k][oc] ----------
__global__ void k_wt(const float* __restrict__ cw) {
    int o = blockIdx.x * 256 + threadIdx.x;
    if (o >= 7077888) return;
    int oc = o & 255;
    int k  = (o >> 8) % 9;
    int ic = (o / 2304) & 255;
    int sl = o / 589824;
    g_convwT[o] = cw[((sl * 256 + oc) * 256 + ic) * 9 + k];
}

// ---- per-ROI: ROI-align pool + 4x(conv3x3 + LN + ReLU), all in SMEM -------
__global__ void __launch_bounds__(256) k_head(int s, const float* __restrict__ lng,
                                              const float* __restrict__ lnb) {
    extern __shared__ float sm[];
    float* xa   = sm;              // 12544  [c][p]
    float* xb   = sm + 12544;      // 12544
    float* mW   = sm + 25088;      // 784  (196 samples * 4 weights)
    float* mu   = sm + 25872;      // 49
    float* rstd = sm + 25921;      // 49
    int*   mI   = (int*)(sm + 25970); // 784 ints

    int r = blockIdx.x, tid = threadIdx.x;

    float b0 = g_boxes[r * 4 + 0], b1 = g_boxes[r * 4 + 1];
    float b2 = g_boxes[r * 4 + 2], b3 = g_boxes[r * 4 + 3];

    // level assignment
    float area = (b2 - b0) * (b3 - b1);
    float lv = floorf(4.0f + log2f(sqrtf(fmaxf(area, 1.0f)) / 224.0f + 1e-8f));
    int lvl = min(max((int)lv, 2), 5) - 2;
    const int   Ht[4]   = {200, 100, 50, 25};
    const float sct[4]  = {0.25f, 0.125f, 0.0625f, 0.03125f};
    const int   offt[4] = {0, 10240000, 12800000, 13440000};
    int H = Ht[lvl], W = H;
    float scale = sct[lvl];
    const float* F = g_featT + offt[lvl];

    float x1 = b0 * scale, y1 = b1 * scale, x2 = b2 * scale, y2 = b3 * scale;
    float bw = fmaxf(x2 - x1, 1.0f) * (1.0f / 7.0f);
    float bh = fmaxf(y2 - y1, 1.0f) * (1.0f / 7.0f);

    // precompute 196 sample points (49 cells x 2x2)
    if (tid < 196) {
        int p = tid >> 2, q = tid & 3;
        int py = p / 7, px = p % 7;
        int iy = q >> 1, ix = q & 1;
        float y = y1 + ((float)py + ((float)iy + 0.5f) * 0.5f) * bh;
        float x = x1 + ((float)px + ((float)ix + 0.5f) * 0.5f) * bw;
        bool valid = (y > -1.0f) && (y < (float)H) && (x > -1.0f) && (x < (float)W);
        float yc = fminf(fmaxf(y, 0.f), (float)(H - 1));
        float xc = fminf(fmaxf(x, 0.f), (float)(W - 1));
        float yf = floorf(yc), xf = floorf(xc);
        int y0 = (int)yf, x0 = (int)xf;
        int y1i = min(y0 + 1, H - 1), x1i = min(x0 + 1, W - 1);
        float ly = yc - yf, lx = xc - xf;
        float v = valid ? 1.0f : 0.0f;
        mI[tid * 4 + 0] = (y0 * W + x0) * 256;
        mI[tid * 4 + 1] = (y0 * W + x1i) * 256;
        mI[tid * 4 + 2] = (y1i * W + x0) * 256;
        mI[tid * 4 + 3] = (y1i * W + x1i) * 256;
        mW[tid * 4 + 0] = (1.f - ly) * (1.f - lx) * v;
        mW[tid * 4 + 1] = (1.f - ly) * lx * v;
        mW[tid * 4 + 2] = ly * (1.f - lx) * v;
        mW[tid * 4 + 3] = ly * lx * v;
    }
    __syncthreads();

    // pooling: thread = channel
    for (int p = 0; p < 49; ++p) {
        float acc = 0.f;
        #pragma unroll
        for (int q = 0; q < 4; ++q) {
            int m = p * 4 + q;
            acc += mW[m * 4 + 0] * F[mI[m * 4 + 0] + tid]
                 + mW[m * 4 + 1] * F[mI[m * 4 + 1] + tid]
                 + mW[m * 4 + 2] * F[mI[m * 4 + 2] + tid]
                 + mW[m * 4 + 3] * F[mI[m * 4 + 3] + tid];
        }
        xa[tid * 49 + p] = acc * 0.25f;
    }
    __syncthreads();

    float* xin = xa;
    float* xout = xb;
    for (int l = 0; l < 4; ++l) {
        const float* Wl = g_convwT + (size_t)(s * 4 + l) * 2304 * 256;
        float acc[49];
        #pragma unroll
        for (int p = 0; p < 49; ++p) acc[p] = 0.f;

        #pragma unroll 1
        for (int ic = 0; ic < 256; ++ic) {
            const float* xrow = xin + ic * 49;
            const float* wp = Wl + ic * 2304 + tid;
            float wr[9];
            #pragma unroll
            for (int k = 0; k < 9; ++k) wr[k] = wp[k * 256];
            #pragma unroll
            for (int ky = 0; ky < 3; ++ky) {
                #pragma unroll
                for (int kx = 0; kx < 3; ++kx) {
                    float wv = wr[ky * 3 + kx];
                    #pragma unroll
                    for (int py = 0; py < 7; ++py) {
                        int sy = py + ky - 1;
                        if (sy < 0 || sy > 6) continue;
                        #pragma unroll
                        for (int px = 0; px < 7; ++px) {
                            int sx = px + kx - 1;
                            if (sx < 0 || sx > 6) continue;
                            acc[py * 7 + px] = fmaf(wv, xrow[sy * 7 + sx], acc[py * 7 + px]);
                        }
                    }
                }
            }
        }
        #pragma unroll
        for (int p = 0; p < 49; ++p) xout[tid * 49 + p] = acc[p];
        __syncthreads();

        // LayerNorm over channels at each spatial position (two-pass)
        int wid = tid >> 5, lane = tid & 31;
        for (int p = wid; p < 49; p += 8) {
            float sum = 0.f;
            for (int i = lane; i < 256; i += 32) sum += xout[i * 49 + p];
            for (int o = 16; o; o >>= 1) sum += __shfl_xor_sync(0xffffffffu, sum, o);
            float m = sum * (1.0f / 256.0f);
            float vs = 0.f;
            for (int i = lane; i < 256; i += 32) {
                float d = xout[i * 49 + p] - m;
                vs += d * d;
            }
            for (int o = 16; o; o >>= 1) vs += __shfl_xor_sync(0xffffffffu, vs, o);
            if (lane == 0) {
                mu[p] = m;
                rstd[p] = rsqrtf(vs * (1.0f / 256.0f) + 1e-6f);
            }
        }
        __syncthreads();
        float g = lng[(s * 4 + l) * 256 + tid];
        float bb = lnb[(s * 4 + l) * 256 + tid];
        #pragma unroll
        for (int p = 0; p < 49; ++p) {
            float v = (xout[tid * 49 + p] - mu[p]) * rstd[p] * g + bb;
            xout[tid * 49 + p] = fmaxf(v, 0.f);
        }
        __syncthreads();
        float* t = xin; xin = xout; xout = t;
    }

    // xin holds final [c][p]; flatten order c*49+p matches reference reshape
    #pragma unroll
    for (int p = 0; p < 49; ++p)
        g_xfeat[(size_t)r * FIN + tid * 49 + p] = xin[tid * 49 + p];
}

// ---------------- FC GEMM: h[512,1024] = relu(x[512,12544] @ W^T + b) ------
__global__ void __launch_bounds__(256) k_fc(int s, const float* __restrict__ fcw,
                                            const float* __restrict__ fcb) {
    __shared__ float As[16][68];
    __shared__ float Bs[16][68];
    int mB = blockIdx.x * 64, nB = blockIdx.y * 64;
    int tid = threadIdx.x;
    int tx = tid & 15, ty = tid >> 4;
    float acc[4][4];
    #pragma unroll
    for (int i = 0; i < 4; ++i)
        #pragma unroll
        for (int j = 0; j < 4; ++j) acc[i][j] = 0.f;

    const float* Bmat = fcw + (size_t)s * FCDIM * FIN;
    for (int kb = 0; kb < FIN; kb += 16) {
        #pragma unroll
        for (int i = 0; i < 4; ++i) {
            int q = tid + 256 * i;
            int row = q >> 4, kk = q & 15;
            As[kk][row] = g_xfeat[(size_t)(mB + row) * FIN + kb + kk];
            Bs[kk][row] = Bmat[(size_t)(nB + row) * FIN + kb + kk];
        }
        __syncthreads();
        #pragma unroll
        for (int kk = 0; kk < 16; ++kk) {
            float a[4], b[4];
            #pragma unroll
            for (int i = 0; i < 4; ++i) a[i] = As[kk][ty * 4 + i];
            #pragma unroll
            for (int j = 0; j < 4; ++j) b[j] = Bs[kk][tx * 4 + j];
            #pragma unroll
            for (int i = 0; i < 4; ++i)
                #pragma unroll
                for (int j = 0; j < 4; ++j) acc[i][j] = fmaf(a[i], b[j], acc[i][j]);
        }
        __syncthreads();
    }
    #pragma unroll
    for (int i = 0; i < 4; ++i) {
        int m = mB + ty * 4 + i;
        #pragma unroll
        for (int j = 0; j < 4; ++j) {
            int n = nB + tx * 4 + j;
            g_h[m * FCDIM + n] = fmaxf(acc[i][j] + fcb[s * FCDIM + n], 0.f);
        }
    }
}

// ------- cls/box heads + softmax accumulate + box decode (per ROI) ---------
__global__ void k_clsbox(int s, const float* __restrict__ clsw, const float* __restrict__ clsb,
                         const float* __restrict__ boxw, const float* __restrict__ boxb) {
    __shared__ float v[11];
    int r = blockIdx.x;
    int tid = threadIdx.x, w = tid >> 5, lane = tid & 31;
    const float* h = g_h + (size_t)r * FCDIM;
    if (w < 11) {
        const float* wgt = (w < 7) ? (clsw + (size_t)(s * 7 + w) * FCDIM)
                                   : (boxw + (size_t)(s * 4 + (w - 7)) * FCDIM);
        float sum = 0.f;
        for (int i = lane; i < FCDIM; i += 32) sum += h[i] * wgt[i];
        for (int o = 16; o; o >>= 1) sum += __shfl_xor_sync(0xffffffffu, sum, o);
        if (lane == 0)
            v[w] = sum + ((w < 7) ? clsb[s * 7 + w] : boxb[s * 4 + (w - 7)]);
    }
    __syncthreads();
    if (tid == 0) {
        // softmax over 7 classes, accumulate
        float mx = v[0];
        #pragma unroll
        for (int j = 1; j < 7; ++j) mx = fmaxf(mx, v[j]);
        float e[7], se = 0.f;
        #pragma unroll
        for (int j = 0; j < 7; ++j) { e[j] = expf(v[j] - mx); se += e[j]; }
        float inv = 1.0f / se;
        #pragma unroll
        for (int j = 0; j < 7; ++j) g_ssum[r * 7 + j] += e[j] * inv;

        // decode boxes with per-stage weights
        const float wx[3] = {10.f, 20.f, 30.f};
        const float wwh[3] = {5.f, 10.f, 15.f};
        float b0 = g_boxes[r * 4 + 0], b1 = g_boxes[r * 4 + 1];
        float b2 = g_boxes[r * 4 + 2], b3 = g_boxes[r * 4 + 3];
        float ax = (b0 + b2) * 0.5f, ay = (b1 + b3) * 0.5f;
        float aw = b2 - b0, ah = b3 - b1;
        float dx = v[7] / wx[s], dy = v[8] / wx[s];
        float dw = fminf(v[9] / wwh[s], DW_MAX);
        float dh = fminf(v[10] / wwh[s], DW_MAX);
        float cx = dx * aw + ax, cy = dy * ah + ay;
        float nw = expf(dw) * aw, nh = expf(dh) * ah;
        float nx1 = cx - nw * 0.5f, ny1 = cy - nh * 0.5f;
        float nx2 = cx + nw * 0.5f, ny2 = cy + nh * 0.5f;
        g_boxes[r * 4 + 0] = fminf(fmaxf(nx1, 0.f), 800.f);
        g_boxes[r * 4 + 1] = fminf(fmaxf(ny1, 0.f), 800.f);
        g_boxes[r * 4 + 2] = fminf(fmaxf(nx2, 0.f), 800.f);
        g_boxes[r * 4 + 3] = fminf(fmaxf(ny2, 0.f), 800.f);
    }
}

// ------------------ NMS (exact replica of reference scan) ------------------
__global__ void __launch_bounds__(512) k_nms(float* __restrict__ out) {
    __shared__ float sc[3072];
    __shared__ float sb[NPROP * 4];
    __shared__ float sa[NPROP];
    __shared__ float rv[16];
    __shared__ int   ri[16];
    __shared__ int   bIdx;
    __shared__ int   oIdx[100];
    __shared__ float oVal[100];
    int tid = threadIdx.x;

    if (tid < NPROP) {
        float b0 = g_boxes[tid * 4 + 0], b1 = g_boxes[tid * 4 + 1];
        float b2 = g_boxes[tid * 4 + 2], b3 = g_boxes[tid * 4 + 3];
        sb[tid * 4 + 0] = b0; sb[tid * 4 + 1] = b1;
        sb[tid * 4 + 2] = b2; sb[tid * 4 + 3] = b3;
        sa[tid] = (b2 - b0) * (b3 - b1);
    }
    for (int c = tid; c < 3072; c += 512) {
        int col = c >> 9, r = c & 511;
        float s = g_ssum[r * 7 + col] * (1.0f / 3.0f);
        sc[c] = (s > 0.05f) ? s : -1.0f;
    }
    __syncthreads();

    for (int it = 0; it < 100; ++it) {
        // argmax with first-index tie-break (matches jnp.argmax)
        float bv = NEG_INF;
        int bi = 0x7fffffff;
        #pragma unroll
        for (int q = 0; q < 6; ++q) {
            int c = tid * 6 + q;
            float v = sc[c];
            if (v > bv || (v == bv && c < bi)) { bv = v; bi = c; }
        }
        for (int o = 16; o; o >>= 1) {
            float ov = __shfl_xor_sync(0xffffffffu, bv, o);
            int oi = __shfl_xor_sync(0xffffffffu, bi, o);
            if (ov > bv || (ov == bv && oi < bi)) { bv = ov; bi = oi; }
        }
        int w = tid >> 5, lane = tid & 31;
        if (lane == 0) { rv[w] = bv; ri[w] = bi; }
        __syncthreads();
        if (tid == 0) {
            float fv = rv[0]; int fi = ri[0];
            for (int k = 1; k < 16; ++k)
                if (rv[k] > fv || (rv[k] == fv && ri[k] < fi)) { fv = rv[k]; fi = ri[k]; }
            bIdx = fi; oIdx[it] = fi; oVal[it] = fv;
        }
        __syncthreads();

        int i = bIdx;
        int col = i >> 9, rr = i & 511;
        float ib0 = sb[rr * 4 + 0], ib1 = sb[rr * 4 + 1];
        float ib2 = sb[rr * 4 + 2], ib3 = sb[rr * 4 + 3];
        float ia = sa[rr];
        if (tid < NPROP) {
            int j = (col << 9) + tid;   // suppression only affects same label chunk
            float xx1 = fmaxf(ib0, sb[tid * 4 + 0]);
            float yy1 = fmaxf(ib1, sb[tid * 4 + 1]);
            float xx2 = fminf(ib2, sb[tid * 4 + 2]);
            float yy2 = fminf(ib3, sb[tid * 4 + 3]);
            float inter = fmaxf(xx2 - xx1, 0.f) * fmaxf(yy2 - yy1, 0.f);
            float iou = inter / (ia + sa[tid] - inter + 1e-9f);
            if (iou > 0.5f) sc[j] = NEG_INF;
            if (tid == rr) sc[i] = NEG_INF;  // explicit .at[i].set(-inf)
        }
        __syncthreads();
    }

    // outputs: boxes [0..399], scores [400..499], labels [500..599]
    if (tid < 100) {
        int i = oIdx[tid];
        float sv = oVal[tid];
        bool valid = sv > 0.05f;
        int r = i & 511, col = i >> 9;
        float f = valid ? 1.f : 0.f;
        out[tid * 4 + 0] = sb[r * 4 + 0] * f;
        out[tid * 4 + 1] = sb[r * 4 + 1] * f;
        out[tid * 4 + 2] = sb[r * 4 + 2] * f;
        out[tid * 4 + 3] = sb[r * 4 + 3] * f;
        out[400 + tid] = valid ? sv : 0.f;
        out[500 + tid] = valid ? (float)(col + 1) : 0.f;
    }
}

// ---------------------------------------------------------------------------
extern "C" void kernel_launch(void* const* d_in, const int* in_sizes, int n_in,
                              void* d_out, int out_size) {
    const float* p2   = (const float*)d_in[0];
    const float* p3   = (const float*)d_in[1];
    const float* p4   = (const float*)d_in[2];
    const float* p5   = (const float*)d_in[3];
    const float* prop = (const float*)d_in[4];
    const float* cw   = (const float*)d_in[5];
    const float* lng  = (const float*)d_in[6];
    const float* lnb  = (const float*)d_in[7];
    const float* fcw  = (const float*)d_in[8];
    const float* fcb  = (const float*)d_in[9];
    const float* clsw = (const float*)d_in[10];
    const float* clsb = (const float*)d_in[11];
    const float* boxw = (const float*)d_in[12];
    const float* boxb = (const float*)d_in[13];

    const int smemHead = 25970 * 4 + 784 * 4;  // 107,016 B
    cudaFuncSetAttribute(k_head, cudaFuncAttributeMaxDynamicSharedMemorySize, smemHead);

    k_init<<<14, 256>>>(prop);

    dim3 tb(32, 8);
    k_transpose<<<dim3(1250, 8), tb>>>(p2, 40000, 0);
    k_transpose<<<dim3(313, 8),  tb>>>(p3, 10000, 10240000);
    k_transpose<<<dim3(79, 8),   tb>>>(p4, 2500, 12800000);
    k_transpose<<<dim3(20, 8),   tb>>>(p5, 625, 13440000);

    k_wt<<<27648, 256>>>(cw);

    for (int s = 0; s < 3; ++s) {
        k_head<<<512, 256, smemHead>>>(s, lng, lnb);
        k_fc<<<dim3(8, 16), 256>>>(s, fcw, fcb);
        k_clsbox<<<512, 352>>>(s, clsw, clsb, boxw, boxb);
    }

    k_nms<<<1, 512>>>((float*)d_out);
}